// round 2
// baseline (speedup 1.0000x reference)
#include <cuda_runtime.h>
#include <math.h>

// Problem shape (fixed by the dataset)
#define BB 16
#define NN 8192
#define DD 128
#define HH 64
#define EE 64
#define EPS_LN 1e-5f

#define BLK1 64               // blocks per batch in pass 1
#define ROWS1 (NN / BLK1)     // 128 rows per pass-1 block
#define TILE 64               // rows per pass-3 tile
#define XDST 256              // Xd row stride in floats (2*DD, duplicated)

// ---------------- scratch (__device__ globals; no allocation allowed) -------
__device__ float  d_partial[BB][BLK1][DD];  // per-block column sums of (x-mu)*rstd
__device__ float2 d_stats[BB * NN];         // per-row {mu, rstd}
__device__ float  d_G[BB][DD * EE];         // folded per-batch matrix ln_w[d]*M_b[d][e]
__device__ float  d_u[BB][EE];              // col sums of G
__device__ float  d_h[BB][EE];              // constant epilogue term

// ============================ Pass 1: row stats + column sums ===============
// 2 rows per iteration -> 4 independent shuffle-reduce chains in flight.
__global__ void k1_stats(const float* __restrict__ x) {
    int b    = blockIdx.y;
    int w    = threadIdx.x >> 5;
    int lane = threadIdx.x & 31;
    int rowbase = blockIdx.x * ROWS1 + w * (ROWS1 / 8);

    const float4* xb = (const float4*)(x + (size_t)b * NN * DD);

    float4 acc = make_float4(0.f, 0.f, 0.f, 0.f);
    #pragma unroll
    for (int rr = 0; rr < ROWS1 / 8; rr += 2) {
        int row0 = rowbase + rr;
        float4 v0 = xb[(row0 + 0) * (DD / 4) + lane];
        float4 v1 = xb[(row0 + 1) * (DD / 4) + lane];
        float s0 = v0.x + v0.y + v0.z + v0.w;
        float q0 = v0.x * v0.x + v0.y * v0.y + v0.z * v0.z + v0.w * v0.w;
        float s1 = v1.x + v1.y + v1.z + v1.w;
        float q1 = v1.x * v1.x + v1.y * v1.y + v1.z * v1.z + v1.w * v1.w;
        #pragma unroll
        for (int o = 16; o > 0; o >>= 1) {
            s0 += __shfl_xor_sync(0xffffffffu, s0, o);
            q0 += __shfl_xor_sync(0xffffffffu, q0, o);
            s1 += __shfl_xor_sync(0xffffffffu, s1, o);
            q1 += __shfl_xor_sync(0xffffffffu, q1, o);
        }
        float mu0   = s0 * (1.0f / DD);
        float rstd0 = rsqrtf(q0 * (1.0f / DD) - mu0 * mu0 + EPS_LN);
        float mu1   = s1 * (1.0f / DD);
        float rstd1 = rsqrtf(q1 * (1.0f / DD) - mu1 * mu1 + EPS_LN);
        if (lane == 0) d_stats[b * NN + row0]     = make_float2(mu0, rstd0);
        if (lane == 1) d_stats[b * NN + row0 + 1] = make_float2(mu1, rstd1);
        acc.x += (v0.x - mu0) * rstd0 + (v1.x - mu1) * rstd1;
        acc.y += (v0.y - mu0) * rstd0 + (v1.y - mu1) * rstd1;
        acc.z += (v0.z - mu0) * rstd0 + (v1.z - mu1) * rstd1;
        acc.w += (v0.w - mu0) * rstd0 + (v1.w - mu1) * rstd1;
    }

    __shared__ float sred[8][DD];
    ((float4*)sred[w])[lane] = acc;
    __syncthreads();
    if (threadIdx.x < DD) {
        float s = 0.f;
        #pragma unroll
        for (int ww = 0; ww < 8; ww++) s += sred[ww][threadIdx.x];
        d_partial[b][blockIdx.x][threadIdx.x] = s;
    }
}

// ============================ Pass 2: per-batch fold =========================
#define SWRP 65
#define K2_SMEM_FLOATS (DD * SWRP /*sWr*/ + HH * EE /*sP*/ + DD * SWRP /*sM*/ + DD + HH + EE)

__global__ void __launch_bounds__(256) k2_prep(
    const float* __restrict__ ln_w, const float* __restrict__ ln_b,
    const float* __restrict__ Wl,   const float* __restrict__ bl,
    const float* __restrict__ Wr,   const float* __restrict__ br,
    const float* __restrict__ Wo,   const float* __restrict__ bo) {
    extern __shared__ float sm[];
    float* sWr = sm;                    // [DD][SWRP]
    float* sP  = sWr + DD * SWRP;       // [HH][EE]
    float* sM  = sP + HH * EE;          // [DD][SWRP]
    float* sx  = sM + DD * SWRP;        // [DD]
    float* slm = sx + DD;               // [HH]
    float* sc  = slm + HH;              // [EE]

    int b = blockIdx.x, tid = threadIdx.x;

    for (int i = tid; i < DD * HH; i += 256) {
        int d = i >> 6, h = i & 63;
        sWr[d * SWRP + h] = Wr[i];
    }
    if (tid < DD) {
        float s = 0.f;
        for (int p = 0; p < BLK1; p++) s += d_partial[b][p][tid];
        sx[tid] = ln_w[tid] * (s * (1.0f / NN)) + ln_b[tid];
    }
    __syncthreads();
    if (tid < HH) {
        float a = bl[tid];
        for (int d = 0; d < DD; d++) a += sx[d] * Wl[d * HH + tid];
        slm[tid] = a;
    }
    __syncthreads();
    for (int i = tid; i < HH * EE; i += 256) sP[i] = slm[i / EE] * Wo[i];
    __syncthreads();
    if (tid < EE) {
        float a = bo[tid];
        for (int h = 0; h < HH; h++) a += br[h] * sP[h * EE + tid];
        sc[tid] = a;
    }
    {
        int d = tid >> 1, e0 = (tid & 1) * 32;
        float acc[32];
        #pragma unroll
        for (int e = 0; e < 32; e++) acc[e] = 0.f;
        for (int h = 0; h < HH; h++) {
            float wr = sWr[d * SWRP + h];
            const float* p = &sP[h * EE + e0];
            #pragma unroll
            for (int e = 0; e < 32; e++) acc[e] += wr * p[e];
        }
        float* m = &sM[d * SWRP + e0];
        #pragma unroll
        for (int e = 0; e < 32; e++) m[e] = acc[e];
    }
    __syncthreads();
    float* Gb = d_G[b];
    for (int i = tid; i < DD * EE; i += 256) {
        int d = i >> 6, e = i & 63;
        Gb[i] = ln_w[d] * sM[d * SWRP + e];
    }
    if (tid < EE) {
        float su = 0.f, shv = 0.f;
        for (int d = 0; d < DD; d++) {
            float m = sM[d * SWRP + tid];
            su  += ln_w[d] * m;
            shv += ln_b[d] * m;
        }
        d_u[b][tid] = su;
        d_h[b][tid] = shv + sc[tid];
    }
}

// ============================ Pass 3: fused main GEMM ========================
// out[b,n,e] = rstd_n*( (x_row @ G_b)[e] - mu_n*u[e] ) + h[e]
// Xd holds x duplicated per element ({x,x}) so f32x2 broadcast operands come
// straight from LDS.128 — zero packing movs in the inner loop.
#define K3_SMEM_FLOATS (TILE * XDST /*Xd*/ + DD * EE /*Gs*/ + EE + EE + 2 * TILE)

__global__ void __launch_bounds__(256, 2) k3_gemm(const float* __restrict__ x,
                                                  float* __restrict__ out) {
    extern __shared__ float sm[];
    float*  Xd  = sm;                       // [TILE][2*DD]  duplicated x
    float*  Gs  = Xd + TILE * XDST;         // [DD][EE] row-major
    float*  su  = Gs + DD * EE;             // [EE]
    float*  sh  = su + EE;                  // [EE]
    float2* sst = (float2*)(sh + EE);       // [TILE] {mu, rstd}

    int b    = blockIdx.y;
    int tile = blockIdx.x;
    int tid  = threadIdx.x;
    int row0 = tile * TILE;

    // load G (coalesced float4)
    {
        const float4* g4  = (const float4*)d_G[b];
        float4*       Gs4 = (float4*)Gs;
        #pragma unroll
        for (int i = 0; i < (DD * EE / 4) / 256; i++)
            Gs4[tid + i * 256] = g4[tid + i * 256];
    }
    // load X tile, store duplicated: Xd[r][2k] = Xd[r][2k+1] = x[r][k]
    {
        const float4* xb = (const float4*)(x + ((size_t)b * NN + row0) * DD);
        #pragma unroll
        for (int i = 0; i < (TILE * DD / 4) / 256; i++) {
            int fid = tid + i * 256;
            int r = fid >> 5, kq = fid & 31;
            float4 v = xb[r * (DD / 4) + kq];
            float* dst = &Xd[r * XDST + 8 * kq];
            *(float4*)(dst + 0) = make_float4(v.x, v.x, v.y, v.y);
            *(float4*)(dst + 4) = make_float4(v.z, v.z, v.w, v.w);
        }
    }
    if (tid < EE) { su[tid] = d_u[b][tid]; sh[tid] = d_h[b][tid]; }
    if (tid < TILE) sst[tid] = d_stats[b * NN + row0 + tid];
    __syncthreads();

    int ty = tid >> 4, tx = tid & 15;   // 16x16 threads; 4 rows x 4 e each
    unsigned long long acc[4][2];       // acc[row][epair]: (e0,e1),(e2,e3)
    #pragma unroll
    for (int i = 0; i < 4; i++) { acc[i][0] = 0ull; acc[i][1] = 0ull; }

    const float* xrow[4];
    #pragma unroll
    for (int i = 0; i < 4; i++) xrow[i] = &Xd[(4 * ty + i) * XDST];
    const float* gb = &Gs[4 * tx];

    #pragma unroll 8
    for (int kp = 0; kp < DD / 2; kp++) {          // k = 2*kp, 2*kp+1
        ulonglong2 g0 = *(const ulonglong2*)(gb + (2 * kp)     * EE);
        ulonglong2 g1 = *(const ulonglong2*)(gb + (2 * kp + 1) * EE);
        #pragma unroll
        for (int i = 0; i < 4; i++) {
            ulonglong2 xv = *(const ulonglong2*)(xrow[i] + 4 * kp);
            // xv.x = {x[k],x[k]}, xv.y = {x[k+1],x[k+1]}
            asm("fma.rn.f32x2 %0, %1, %2, %0;" : "+l"(acc[i][0]) : "l"(xv.x), "l"(g0.x));
            asm("fma.rn.f32x2 %0, %1, %2, %0;" : "+l"(acc[i][1]) : "l"(xv.x), "l"(g0.y));
            asm("fma.rn.f32x2 %0, %1, %2, %0;" : "+l"(acc[i][0]) : "l"(xv.y), "l"(g1.x));
            asm("fma.rn.f32x2 %0, %1, %2, %0;" : "+l"(acc[i][1]) : "l"(xv.y), "l"(g1.y));
        }
    }

    // epilogue: out = rstd*(acc - mu*u) + h
    #pragma unroll
    for (int i = 0; i < 4; i++) {
        int r = 4 * ty + i;
        float2 st = sst[r];
        float mu = st.x, rstd = st.y;
        unsigned lo0, hi0, lo1, hi1;
        asm("mov.b64 {%0,%1}, %2;" : "=r"(lo0), "=r"(hi0) : "l"(acc[i][0]));
        asm("mov.b64 {%0,%1}, %2;" : "=r"(lo1), "=r"(hi1) : "l"(acc[i][1]));
        int e0 = 4 * tx;
        float4 o;
        o.x = rstd * (__uint_as_float(lo0) - mu * su[e0 + 0]) + sh[e0 + 0];
        o.y = rstd * (__uint_as_float(hi0) - mu * su[e0 + 1]) + sh[e0 + 1];
        o.z = rstd * (__uint_as_float(lo1) - mu * su[e0 + 2]) + sh[e0 + 2];
        o.w = rstd * (__uint_as_float(hi1) - mu * su[e0 + 3]) + sh[e0 + 3];
        *(float4*)&out[(((size_t)b * NN + row0 + r) * EE) + e0] = o;
    }
}

// ============================ launch =========================================
extern "C" void kernel_launch(void* const* d_in, const int* in_sizes, int n_in,
                              void* d_out, int out_size) {
    const float* x    = (const float*)d_in[0];
    const float* ln_w = (const float*)d_in[1];
    const float* ln_b = (const float*)d_in[2];
    const float* Wl   = (const float*)d_in[3];
    const float* bl   = (const float*)d_in[4];
    const float* Wr   = (const float*)d_in[5];
    const float* br   = (const float*)d_in[6];
    const float* Wo   = (const float*)d_in[7];
    const float* bo   = (const float*)d_in[8];
    float* out = (float*)d_out;

    const int k2_smem = K2_SMEM_FLOATS * (int)sizeof(float);
    const int k3_smem = K3_SMEM_FLOATS * (int)sizeof(float);
    cudaFuncSetAttribute(k2_prep, cudaFuncAttributeMaxDynamicSharedMemorySize, k2_smem);
    cudaFuncSetAttribute(k3_gemm, cudaFuncAttributeMaxDynamicSharedMemorySize, k3_smem);

    k1_stats<<<dim3(BLK1, BB), 256>>>(x);
    k2_prep<<<BB, 256, k2_smem>>>(ln_w, ln_b, Wl, bl, Wr, br, Wo, bo);
    k3_gemm<<<dim3(NN / TILE, BB), 256, k3_smem>>>(x, out);
}

// round 3
// speedup vs baseline: 1.1567x; 1.1567x over previous
#include <cuda_runtime.h>
#include <math.h>

// Problem shape (fixed by the dataset)
#define BB 16
#define NN 8192
#define DD 128
#define HH 64
#define EE 64
#define EPS_LN 1e-5f

#define BLK1 64               // blocks per batch in pass 1
#define ROWS1 (NN / BLK1)     // 128 rows per pass-1 block
#define TILE 128              // rows per pass-3 tile
#define XP 132                // padded Xs row stride (floats)

// ---------------- scratch (__device__ globals; no allocation allowed) -------
__device__ float  d_partial[BB][BLK1][DD];  // per-block column sums of (x-mu)*rstd
__device__ float2 d_stats[BB * NN];         // per-row {mu, rstd}
__device__ float  d_lm[BB][HH];             // left-mean vector
__device__ float  d_c[BB][EE];              // bias-fold constant
__device__ float  d_M[BB][DD * EE];         // M = Wr diag(lm) Wo
__device__ float  d_G[BB][DD * EE];         // G = diag(ln_w) M
__device__ float  d_u[BB][EE];              // col sums of G
__device__ float  d_h[BB][EE];              // constant epilogue term

// ============================ Pass 1: row stats + column sums ===============
// 4 rows per iteration -> 8 independent shuffle-reduce chains in flight.
__global__ void k1_stats(const float* __restrict__ x) {
    int b    = blockIdx.y;
    int w    = threadIdx.x >> 5;
    int lane = threadIdx.x & 31;
    int rowbase = blockIdx.x * ROWS1 + w * (ROWS1 / 8);

    const float4* xb = (const float4*)(x + (size_t)b * NN * DD);

    float4 acc = make_float4(0.f, 0.f, 0.f, 0.f);
    #pragma unroll
    for (int rr = 0; rr < ROWS1 / 8; rr += 4) {
        int row0 = rowbase + rr;
        float4 v[4];
        float s[4], q[4];
        #pragma unroll
        for (int j = 0; j < 4; j++) {
            v[j] = xb[(row0 + j) * (DD / 4) + lane];
            s[j] = v[j].x + v[j].y + v[j].z + v[j].w;
            q[j] = v[j].x * v[j].x + v[j].y * v[j].y + v[j].z * v[j].z + v[j].w * v[j].w;
        }
        #pragma unroll
        for (int o = 16; o > 0; o >>= 1) {
            #pragma unroll
            for (int j = 0; j < 4; j++) {
                s[j] += __shfl_xor_sync(0xffffffffu, s[j], o);
                q[j] += __shfl_xor_sync(0xffffffffu, q[j], o);
            }
        }
        #pragma unroll
        for (int j = 0; j < 4; j++) {
            float mu   = s[j] * (1.0f / DD);
            float rstd = rsqrtf(q[j] * (1.0f / DD) - mu * mu + EPS_LN);
            if (lane == j) d_stats[b * NN + row0 + j] = make_float2(mu, rstd);
            acc.x += (v[j].x - mu) * rstd;
            acc.y += (v[j].y - mu) * rstd;
            acc.z += (v[j].z - mu) * rstd;
            acc.w += (v[j].w - mu) * rstd;
        }
    }

    __shared__ float sred[8][DD];
    ((float4*)sred[w])[lane] = acc;
    __syncthreads();
    if (threadIdx.x < DD) {
        float s = 0.f;
        #pragma unroll
        for (int ww = 0; ww < 8; ww++) s += sred[ww][threadIdx.x];
        d_partial[b][blockIdx.x][threadIdx.x] = s;
    }
}

// ============================ Pass 2a: xbar -> lm, c (per batch) =============
__global__ void __launch_bounds__(128) k2a(
    const float* __restrict__ ln_w, const float* __restrict__ ln_b,
    const float* __restrict__ Wl,   const float* __restrict__ bl,
    const float* __restrict__ br,
    const float* __restrict__ Wo,   const float* __restrict__ bo) {
    __shared__ float sx[DD];
    __shared__ float slm[HH];
    int b = blockIdx.x, tid = threadIdx.x;

    {
        float s = 0.f;
        #pragma unroll 8
        for (int p = 0; p < BLK1; p++) s += d_partial[b][p][tid];
        sx[tid] = ln_w[tid] * (s * (1.0f / NN)) + ln_b[tid];
    }
    __syncthreads();
    if (tid < HH) {
        float a = bl[tid];
        #pragma unroll 8
        for (int d = 0; d < DD; d++) a += sx[d] * Wl[d * HH + tid];
        slm[tid] = a;
        d_lm[b][tid] = a;
    }
    __syncthreads();
    if (tid < EE) {
        float a = bo[tid];
        #pragma unroll 8
        for (int h = 0; h < HH; h++) a += br[h] * slm[h] * Wo[h * EE + tid];
        d_c[b][tid] = a;
    }
}

// ============================ Pass 2b: M, G (32 x 16 blocks) ================
// Block handles 4 d-rows x 64 e. M[d][e] = sum_h Wr[d][h]*lm[h]*Wo[h][e].
__global__ void __launch_bounds__(256) k2b(
    const float* __restrict__ ln_w,
    const float* __restrict__ Wr, const float* __restrict__ Wo) {
    __shared__ float sP[HH * EE];   // lm[h]*Wo[h][e]
    __shared__ float sWr[4 * HH];
    int b  = blockIdx.y;
    int d0 = blockIdx.x * 4;
    int tid = threadIdx.x;

    #pragma unroll
    for (int i = tid; i < HH * EE; i += 256)
        sP[i] = d_lm[b][i >> 6] * Wo[i];
    sWr[tid] = Wr[(d0 + (tid >> 6)) * HH + (tid & 63)];
    __syncthreads();

    int d_l = tid >> 6, e = tid & 63;
    float acc = 0.f;
    #pragma unroll 8
    for (int h = 0; h < HH; h++)
        acc += sWr[d_l * HH + h] * sP[h * EE + e];

    int d = d0 + d_l;
    d_M[b][d * EE + e] = acc;
    d_G[b][d * EE + e] = ln_w[d] * acc;
}

// ============================ Pass 2c: u, h (per batch) ======================
__global__ void __launch_bounds__(64) k2c(const float* __restrict__ ln_b) {
    int b = blockIdx.x, e = threadIdx.x;
    float su = 0.f, sh = 0.f;
    #pragma unroll 8
    for (int d = 0; d < DD; d++) {
        float g = d_G[b][d * EE + e];
        float m = d_M[b][d * EE + e];
        su += g;
        sh += ln_b[d] * m;
    }
    d_u[b][e] = su;
    d_h[b][e] = sh + d_c[b][e];
}

// ============================ Pass 3: fused main GEMM ========================
// out[b,n,e] = rstd_n*( (x_row @ G_b)[e] - mu_n*u[e] ) + h[e]
// 128 threads, 8 rows x 8 cols per thread. Rows interleaved stride 16 so the
// four ty addresses per warp land in distinct 16B bank slots (conflict-free).
#define K3_SMEM_FLOATS (DD * EE /*Gs*/ + TILE * XP /*Xs*/ + EE + EE + 2 * TILE)

__global__ void __launch_bounds__(128, 2) k3_gemm(const float* __restrict__ x,
                                                  float* __restrict__ out) {
    extern __shared__ float sm[];
    float*  Gs  = sm;                       // [DD][EE] row-major
    float*  Xs  = Gs + DD * EE;             // [TILE][XP]
    float*  su  = Xs + TILE * XP;           // [EE]
    float*  sh  = su + EE;                  // [EE]
    float2* sst = (float2*)(sh + EE);       // [TILE] {mu, rstd}

    int b    = blockIdx.y;
    int tile = blockIdx.x;
    int tid  = threadIdx.x;
    int row0 = tile * TILE;

    // load G (coalesced float4): 16 per thread
    {
        const float4* g4  = (const float4*)d_G[b];
        float4*       Gs4 = (float4*)Gs;
        #pragma unroll
        for (int i = 0; i < (DD * EE / 4) / 128; i++)
            Gs4[tid + i * 128] = g4[tid + i * 128];
    }
    // load X tile: 32 float4 per thread
    {
        const float4* xb = (const float4*)(x + ((size_t)b * NN + row0) * DD);
        #pragma unroll
        for (int i = 0; i < (TILE * DD / 4) / 128; i++) {
            int fid = tid + i * 128;
            int r = fid >> 5, kq = fid & 31;
            float4 v = xb[r * (DD / 4) + kq];
            *(float4*)&Xs[r * XP + 4 * kq] = v;
        }
    }
    if (tid < EE) { su[tid] = d_u[b][tid]; sh[tid] = d_h[b][tid]; }
    sst[tid] = d_stats[b * NN + row0 + tid];
    __syncthreads();

    int tx = tid & 7;        // 8 thread-cols (e)
    int ty = tid >> 3;       // 16 thread-rows; rows = ty + 16*i
    unsigned long long acc[8][4];     // [row][epair]
    #pragma unroll
    for (int i = 0; i < 8; i++)
        #pragma unroll
        for (int j = 0; j < 4; j++) acc[i][j] = 0ull;

    const float* xbase = &Xs[ty * XP];
    const float* gb    = &Gs[8 * tx];

    #pragma unroll 2
    for (int kc = 0; kc < DD / 4; kc++) {
        int k = 4 * kc;
        float4 xv[8];
        #pragma unroll
        for (int i = 0; i < 8; i++)
            xv[i] = *(const float4*)(xbase + i * (16 * XP) + k);
        #pragma unroll
        for (int kk = 0; kk < 4; kk++) {
            ulonglong2 g0 = *(const ulonglong2*)(gb + (k + kk) * EE);
            ulonglong2 g1 = *(const ulonglong2*)(gb + (k + kk) * EE + 4);
            #pragma unroll
            for (int i = 0; i < 8; i++) {
                float a = (kk == 0) ? xv[i].x : (kk == 1) ? xv[i].y
                        : (kk == 2) ? xv[i].z : xv[i].w;
                unsigned long long ap;
                asm("mov.b64 %0, {%1, %1};" : "=l"(ap) : "r"(__float_as_uint(a)));
                asm("fma.rn.f32x2 %0, %1, %2, %0;" : "+l"(acc[i][0]) : "l"(ap), "l"(g0.x));
                asm("fma.rn.f32x2 %0, %1, %2, %0;" : "+l"(acc[i][1]) : "l"(ap), "l"(g0.y));
                asm("fma.rn.f32x2 %0, %1, %2, %0;" : "+l"(acc[i][2]) : "l"(ap), "l"(g1.x));
                asm("fma.rn.f32x2 %0, %1, %2, %0;" : "+l"(acc[i][3]) : "l"(ap), "l"(g1.y));
            }
        }
    }

    // epilogue: out = rstd*(acc - mu*u) + h
    float u0[8], h0[8];
    #pragma unroll
    for (int j = 0; j < 8; j++) { u0[j] = su[8 * tx + j]; h0[j] = sh[8 * tx + j]; }
    #pragma unroll
    for (int i = 0; i < 8; i++) {
        int r = ty + 16 * i;
        float2 st = sst[r];
        float mu = st.x, rstd = st.y;
        float v[8];
        #pragma unroll
        for (int j = 0; j < 4; j++) {
            unsigned lo, hi;
            asm("mov.b64 {%0,%1}, %2;" : "=r"(lo), "=r"(hi) : "l"(acc[i][j]));
            v[2 * j]     = __uint_as_float(lo);
            v[2 * j + 1] = __uint_as_float(hi);
        }
        float* op = &out[(((size_t)b * NN + row0 + r) * EE) + 8 * tx];
        float4 o0, o1;
        o0.x = rstd * (v[0] - mu * u0[0]) + h0[0];
        o0.y = rstd * (v[1] - mu * u0[1]) + h0[1];
        o0.z = rstd * (v[2] - mu * u0[2]) + h0[2];
        o0.w = rstd * (v[3] - mu * u0[3]) + h0[3];
        o1.x = rstd * (v[4] - mu * u0[4]) + h0[4];
        o1.y = rstd * (v[5] - mu * u0[5]) + h0[5];
        o1.z = rstd * (v[6] - mu * u0[6]) + h0[6];
        o1.w = rstd * (v[7] - mu * u0[7]) + h0[7];
        *(float4*)(op + 0) = o0;
        *(float4*)(op + 4) = o1;
    }
}

// ============================ launch =========================================
extern "C" void kernel_launch(void* const* d_in, const int* in_sizes, int n_in,
                              void* d_out, int out_size) {
    const float* x    = (const float*)d_in[0];
    const float* ln_w = (const float*)d_in[1];
    const float* ln_b = (const float*)d_in[2];
    const float* Wl   = (const float*)d_in[3];
    const float* bl   = (const float*)d_in[4];
    const float* Wr   = (const float*)d_in[5];
    const float* br   = (const float*)d_in[6];
    const float* Wo   = (const float*)d_in[7];
    const float* bo   = (const float*)d_in[8];
    float* out = (float*)d_out;

    const int k3_smem = K3_SMEM_FLOATS * (int)sizeof(float);
    cudaFuncSetAttribute(k3_gemm, cudaFuncAttributeMaxDynamicSharedMemorySize, k3_smem);

    k1_stats<<<dim3(BLK1, BB), 256>>>(x);
    k2a<<<BB, 128>>>(ln_w, ln_b, Wl, bl, br, Wo, bo);
    k2b<<<dim3(DD / 4, BB), 256>>>(ln_w, Wr, Wo);
    k2c<<<BB, 64>>>(ln_b);
    k3_gemm<<<dim3(NN / TILE, BB), 128, k3_smem>>>(x, out);
}

// round 4
// speedup vs baseline: 1.1633x; 1.0057x over previous
#include <cuda_runtime.h>
#include <math.h>

// Problem shape (fixed by the dataset)
#define BB 16
#define NN 8192
#define DD 128
#define HH 64
#define EE 64
#define EPS_LN 1e-5f

#define BLK1 64               // blocks per batch in pass 1
#define ROWS1 (NN / BLK1)     // 128 rows per pass-1 block
#define TILE 128              // rows per pass-3 tile
#define XP 132                // padded Xs row stride (floats)

// ---------------- scratch (__device__ globals; no allocation allowed) -------
__device__ float  d_partial[BB][BLK1][DD];  // per-block column sums of (x-mu)*rstd
__device__ float2 d_stats[BB * NN];         // per-row {mu, rstd}
__device__ float  d_G[BB][DD * EE];         // G = diag(ln_w) Wr diag(lm) Wo
__device__ float  d_u[BB][EE];              // u = (ln_w@Wr ⊙ lm) @ Wo
__device__ float  d_h[BB][EE];              // h = (ln_b@Wr ⊙ lm) @ Wo + c

// ============================ Pass 1: row stats + column sums ===============
__global__ void k1_stats(const float* __restrict__ x) {
    int b    = blockIdx.y;
    int w    = threadIdx.x >> 5;
    int lane = threadIdx.x & 31;
    int rowbase = blockIdx.x * ROWS1 + w * (ROWS1 / 8);

    const float4* xb = (const float4*)(x + (size_t)b * NN * DD);

    float4 acc = make_float4(0.f, 0.f, 0.f, 0.f);
    #pragma unroll
    for (int rr = 0; rr < ROWS1 / 8; rr += 4) {
        int row0 = rowbase + rr;
        float4 v[4];
        float s[4], q[4];
        #pragma unroll
        for (int j = 0; j < 4; j++) {
            v[j] = xb[(row0 + j) * (DD / 4) + lane];
            s[j] = v[j].x + v[j].y + v[j].z + v[j].w;
            q[j] = v[j].x * v[j].x + v[j].y * v[j].y + v[j].z * v[j].z + v[j].w * v[j].w;
        }
        #pragma unroll
        for (int o = 16; o > 0; o >>= 1) {
            #pragma unroll
            for (int j = 0; j < 4; j++) {
                s[j] += __shfl_xor_sync(0xffffffffu, s[j], o);
                q[j] += __shfl_xor_sync(0xffffffffu, q[j], o);
            }
        }
        #pragma unroll
        for (int j = 0; j < 4; j++) {
            float mu   = s[j] * (1.0f / DD);
            float rstd = rsqrtf(q[j] * (1.0f / DD) - mu * mu + EPS_LN);
            if (lane == j) d_stats[b * NN + row0 + j] = make_float2(mu, rstd);
            acc.x += (v[j].x - mu) * rstd;
            acc.y += (v[j].y - mu) * rstd;
            acc.z += (v[j].z - mu) * rstd;
            acc.w += (v[j].w - mu) * rstd;
        }
    }

    __shared__ float sred[8][DD];
    ((float4*)sred[w])[lane] = acc;
    __syncthreads();
    if (threadIdx.x < DD) {
        float s = 0.f;
        #pragma unroll
        for (int ww = 0; ww < 8; ww++) s += sred[ww][threadIdx.x];
        d_partial[b][blockIdx.x][threadIdx.x] = s;
    }
}

// ============================ Pass 2: fold (one kernel, 128 blocks) ==========
// grid (8, BB). Block (bx,b): computes xbar, lm, P=lm⊙Wo redundantly (cheap),
// then G rows [16*bx, 16*bx+16). Block bx==0 additionally computes u, h.
__global__ void __launch_bounds__(256) k2_fold(
    const float* __restrict__ ln_w, const float* __restrict__ ln_b,
    const float* __restrict__ Wl,   const float* __restrict__ bl,
    const float* __restrict__ Wr,   const float* __restrict__ br,
    const float* __restrict__ Wo,   const float* __restrict__ bo) {
    __shared__ float sxa[2][DD];
    __shared__ float sx[DD];
    __shared__ float sr4[4][HH];
    __shared__ float slm[HH];
    __shared__ float sP[HH * EE];
    __shared__ float sWr[16 * HH];
    __shared__ float swv4[4][HH], sbv4[4][HH];

    int b = blockIdx.y, bx = blockIdx.x, tid = threadIdx.x;
    int d0 = bx * 16;

    // xbar (redundant per block)
    {
        int col = tid & 127, hf = tid >> 7;
        float s = 0.f;
        #pragma unroll 8
        for (int p = hf * 32; p < hf * 32 + 32; p++) s += d_partial[b][p][col];
        sxa[hf][col] = s;
    }
    // this block's 16 Wr rows
    #pragma unroll
    for (int i = tid; i < 16 * HH; i += 256)
        sWr[i] = Wr[(d0 + (i >> 6)) * HH + (i & 63)];
    __syncthreads();
    if (tid < DD)
        sx[tid] = ln_w[tid] * ((sxa[0][tid] + sxa[1][tid]) * (1.0f / NN)) + ln_b[tid];
    __syncthreads();

    // lm[h]: 4 threads per h, 32 d each
    {
        int h = tid & 63, q = tid >> 6;
        float a = 0.f;
        #pragma unroll 8
        for (int d = q * 32; d < q * 32 + 32; d++) a += sx[d] * Wl[d * HH + h];
        sr4[q][h] = a;
    }
    __syncthreads();
    if (tid < HH)
        slm[tid] = bl[tid] + sr4[0][tid] + sr4[1][tid] + sr4[2][tid] + sr4[3][tid];
    __syncthreads();

    // P[h][e] = lm[h]*Wo[h][e]
    #pragma unroll
    for (int i = tid; i < HH * EE; i += 256) sP[i] = slm[i >> 6] * Wo[i];
    __syncthreads();

    // G rows: thread -> (d_l = tid>>4, e0 = (tid&15)*4)
    {
        int d_l = tid >> 4, e0 = (tid & 15) * 4;
        float a0 = 0.f, a1 = 0.f, a2 = 0.f, a3 = 0.f;
        #pragma unroll 8
        for (int h = 0; h < HH; h++) {
            float w = sWr[d_l * HH + h];
            const float* p = &sP[h * EE + e0];
            a0 += w * p[0]; a1 += w * p[1]; a2 += w * p[2]; a3 += w * p[3];
        }
        int d = d0 + d_l;
        float lw = ln_w[d];
        float* g = &d_G[b][d * EE + e0];
        g[0] = lw * a0; g[1] = lw * a1; g[2] = lw * a2; g[3] = lw * a3;
    }

    // block 0: u, h
    if (bx == 0) {
        {
            int h = tid & 63, q = tid >> 6;
            float aw = 0.f, ab = 0.f;
            #pragma unroll 8
            for (int d = q * 32; d < q * 32 + 32; d++) {
                float wr = Wr[d * HH + h];
                aw += ln_w[d] * wr;
                ab += ln_b[d] * wr;
            }
            swv4[q][h] = aw; sbv4[q][h] = ab;
        }
        __syncthreads();
        if (tid < EE) {
            int e = tid;
            float su = 0.f, sh = 0.f, sc = bo[e];
            #pragma unroll 8
            for (int h = 0; h < HH; h++) {
                float p  = sP[h * EE + e];
                float wv = swv4[0][h] + swv4[1][h] + swv4[2][h] + swv4[3][h];
                float bv = sbv4[0][h] + sbv4[1][h] + sbv4[2][h] + sbv4[3][h];
                su += wv * p;
                sh += bv * p;
                sc += br[h] * p;
            }
            d_u[b][e] = su;
            d_h[b][e] = sh + sc;
        }
    }
}

// ============================ Pass 3: fused main GEMM ========================
// out[b,n,e] = rstd_n*( (x_row @ G_b)[e] - mu_n*u[e] ) + h[e]
// 256 threads, 4 rows x 8 cols per thread (rows interleaved stride 32).
#define K3_SMEM_FLOATS (DD * EE /*Gs*/ + TILE * XP /*Xs*/ + EE + EE + 2 * TILE)

__global__ void __launch_bounds__(256, 2) k3_gemm(const float* __restrict__ x,
                                                  float* __restrict__ out) {
    extern __shared__ float sm[];
    float*  Gs  = sm;                       // [DD][EE] row-major
    float*  Xs  = Gs + DD * EE;             // [TILE][XP]
    float*  su  = Xs + TILE * XP;           // [EE]
    float*  sh  = su + EE;                  // [EE]
    float2* sst = (float2*)(sh + EE);       // [TILE] {mu, rstd}

    int b    = blockIdx.y;
    int tile = blockIdx.x;
    int tid  = threadIdx.x;
    int row0 = tile * TILE;

    // load G: 8 float4/thread
    {
        const float4* g4  = (const float4*)d_G[b];
        float4*       Gs4 = (float4*)Gs;
        #pragma unroll
        for (int i = 0; i < (DD * EE / 4) / 256; i++)
            Gs4[tid + i * 256] = g4[tid + i * 256];
    }
    // load X tile: 16 float4/thread
    {
        const float4* xb = (const float4*)(x + ((size_t)b * NN + row0) * DD);
        #pragma unroll
        for (int i = 0; i < (TILE * DD / 4) / 256; i++) {
            int fid = tid + i * 256;
            int r = fid >> 5, kq = fid & 31;
            float4 v = xb[r * (DD / 4) + kq];
            *(float4*)&Xs[r * XP + 4 * kq] = v;
        }
    }
    if (tid < EE) { su[tid] = d_u[b][tid]; sh[tid] = d_h[b][tid]; }
    if (tid < TILE) sst[tid] = d_stats[b * NN + row0 + tid];
    __syncthreads();

    int tx = tid & 7;        // 8 thread-cols (8 e each)
    int ty = tid >> 3;       // 32 thread-rows; rows = ty + 32*i
    unsigned long long acc[4][4];     // [row][epair]
    #pragma unroll
    for (int i = 0; i < 4; i++)
        #pragma unroll
        for (int j = 0; j < 4; j++) acc[i][j] = 0ull;

    const float* xbase = &Xs[ty * XP];
    const float* gb    = &Gs[8 * tx];

    #pragma unroll 2
    for (int kc = 0; kc < DD / 4; kc++) {
        int k = 4 * kc;
        float4 xv[4];
        #pragma unroll
        for (int i = 0; i < 4; i++)
            xv[i] = *(const float4*)(xbase + i * (32 * XP) + k);
        #pragma unroll
        for (int kk = 0; kk < 4; kk++) {
            ulonglong2 g0 = *(const ulonglong2*)(gb + (k + kk) * EE);
            ulonglong2 g1 = *(const ulonglong2*)(gb + (k + kk) * EE + 4);
            #pragma unroll
            for (int i = 0; i < 4; i++) {
                float a = (kk == 0) ? xv[i].x : (kk == 1) ? xv[i].y
                        : (kk == 2) ? xv[i].z : xv[i].w;
                unsigned long long ap;
                asm("mov.b64 %0, {%1, %1};" : "=l"(ap) : "r"(__float_as_uint(a)));
                asm("fma.rn.f32x2 %0, %1, %2, %0;" : "+l"(acc[i][0]) : "l"(ap), "l"(g0.x));
                asm("fma.rn.f32x2 %0, %1, %2, %0;" : "+l"(acc[i][1]) : "l"(ap), "l"(g0.y));
                asm("fma.rn.f32x2 %0, %1, %2, %0;" : "+l"(acc[i][2]) : "l"(ap), "l"(g1.x));
                asm("fma.rn.f32x2 %0, %1, %2, %0;" : "+l"(acc[i][3]) : "l"(ap), "l"(g1.y));
            }
        }
    }

    // epilogue: out = rstd*(acc - mu*u) + h
    float u0[8], h0[8];
    #pragma unroll
    for (int j = 0; j < 8; j++) { u0[j] = su[8 * tx + j]; h0[j] = sh[8 * tx + j]; }
    #pragma unroll
    for (int i = 0; i < 4; i++) {
        int r = ty + 32 * i;
        float2 st = sst[r];
        float mu = st.x, rstd = st.y;
        float v[8];
        #pragma unroll
        for (int j = 0; j < 4; j++) {
            unsigned lo, hi;
            asm("mov.b64 {%0,%1}, %2;" : "=r"(lo), "=r"(hi) : "l"(acc[i][j]));
            v[2 * j]     = __uint_as_float(lo);
            v[2 * j + 1] = __uint_as_float(hi);
        }
        float* op = &out[(((size_t)b * NN + row0 + r) * EE) + 8 * tx];
        float4 o0, o1;
        o0.x = rstd * (v[0] - mu * u0[0]) + h0[0];
        o0.y = rstd * (v[1] - mu * u0[1]) + h0[1];
        o0.z = rstd * (v[2] - mu * u0[2]) + h0[2];
        o0.w = rstd * (v[3] - mu * u0[3]) + h0[3];
        o1.x = rstd * (v[4] - mu * u0[4]) + h0[4];
        o1.y = rstd * (v[5] - mu * u0[5]) + h0[5];
        o1.z = rstd * (v[6] - mu * u0[6]) + h0[6];
        o1.w = rstd * (v[7] - mu * u0[7]) + h0[7];
        *(float4*)(op + 0) = o0;
        *(float4*)(op + 4) = o1;
    }
}

// ============================ launch =========================================
extern "C" void kernel_launch(void* const* d_in, const int* in_sizes, int n_in,
                              void* d_out, int out_size) {
    const float* x    = (const float*)d_in[0];
    const float* ln_w = (const float*)d_in[1];
    const float* ln_b = (const float*)d_in[2];
    const float* Wl   = (const float*)d_in[3];
    const float* bl   = (const float*)d_in[4];
    const float* Wr   = (const float*)d_in[5];
    const float* br   = (const float*)d_in[6];
    const float* Wo   = (const float*)d_in[7];
    const float* bo   = (const float*)d_in[8];
    float* out = (float*)d_out;

    const int k3_smem = K3_SMEM_FLOATS * (int)sizeof(float);
    cudaFuncSetAttribute(k3_gemm, cudaFuncAttributeMaxDynamicSharedMemorySize, k3_smem);

    k1_stats<<<dim3(BLK1, BB), 256>>>(x);
    k2_fold<<<dim3(8, BB), 256>>>(ln_w, ln_b, Wl, bl, Wr, br, Wo, bo);
    k3_gemm<<<dim3(NN / TILE, BB), 256, k3_smem>>>(x, out);
}

// round 5
// speedup vs baseline: 1.5703x; 1.3498x over previous
#include <cuda_runtime.h>
#include <math.h>

// Problem shape (fixed by the dataset)
#define BB 16
#define NN 8192
#define DD 128
#define HH 64
#define EE 64
#define EPS_LN 1e-5f

#define BLK1 64               // blocks per batch in pass 1
#define ROWS1 (NN / BLK1)     // 128 rows per pass-1 block
#define TILE 128              // rows per pass-3 tile
#define XP 132                // padded Xs row stride (floats)

// ---------------- scratch (__device__ globals; no allocation allowed) -------
__device__ float  d_partial[BB][BLK1][DD];  // per-block column sums of (x-mu)*rstd
__device__ float2 d_stats[BB * NN];         // per-row {mu, rstd}
__device__ float  d_G[BB][DD * EE];         // G = diag(ln_w) Wr diag(lm) Wo
__device__ float  d_u[BB][EE];              // u = (ln_w@Wr ⊙ lm) @ Wo
__device__ float  d_h[BB][EE];              // h = (ln_b@Wr ⊙ lm) @ Wo + c

// ============================ Pass 1: row stats + column sums ===============
// 8 lanes per row (lane = 4*?? -> rp = lane>>3 row-in-group, c = lane&7 col).
// Row-reduce is a 3-round butterfly within the 8-lane group: 6 SHFLs / 4 rows.
__global__ void k1_stats(const float* __restrict__ x) {
    int b    = blockIdx.y;
    int w    = threadIdx.x >> 5;
    int lane = threadIdx.x & 31;
    int rp   = lane >> 3;     // 0..3: row within 4-row group
    int c    = lane & 7;      // 0..7: float4 column chunk
    int rowbase = blockIdx.x * ROWS1 + w * (ROWS1 / 8);   // 16 rows per warp

    const float4* xb = (const float4*)(x + (size_t)b * NN * DD);

    float4 acc[4];
    #pragma unroll
    for (int j = 0; j < 4; j++) acc[j] = make_float4(0.f, 0.f, 0.f, 0.f);

    #pragma unroll
    for (int it = 0; it < 4; it++) {
        int row = rowbase + it * 4 + rp;
        float4 v[4];
        #pragma unroll
        for (int j = 0; j < 4; j++)
            v[j] = xb[row * (DD / 4) + (c + 8 * j)];
        float s = 0.f, q = 0.f;
        #pragma unroll
        for (int j = 0; j < 4; j++) {
            s += v[j].x + v[j].y + v[j].z + v[j].w;
            q += v[j].x * v[j].x + v[j].y * v[j].y + v[j].z * v[j].z + v[j].w * v[j].w;
        }
        #pragma unroll
        for (int o = 4; o > 0; o >>= 1) {
            s += __shfl_xor_sync(0xffffffffu, s, o);
            q += __shfl_xor_sync(0xffffffffu, q, o);
        }
        float mu   = s * (1.0f / DD);
        float rstd = rsqrtf(q * (1.0f / DD) - mu * mu + EPS_LN);
        if (c == 0) d_stats[b * NN + row] = make_float2(mu, rstd);
        #pragma unroll
        for (int j = 0; j < 4; j++) {
            acc[j].x += (v[j].x - mu) * rstd;
            acc[j].y += (v[j].y - mu) * rstd;
            acc[j].z += (v[j].z - mu) * rstd;
            acc[j].w += (v[j].w - mu) * rstd;
        }
    }

    // per-(warp, rp) column-sum slices; lane's columns are float4 slots c+8j
    __shared__ float sred[32][DD];
    {
        float4* dst = (float4*)sred[w * 4 + rp];
        #pragma unroll
        for (int j = 0; j < 4; j++) dst[c + 8 * j] = acc[j];
    }
    __syncthreads();
    if (threadIdx.x < DD) {
        float s = 0.f;
        #pragma unroll
        for (int k = 0; k < 32; k++) s += sred[k][threadIdx.x];
        d_partial[b][blockIdx.x][threadIdx.x] = s;
    }
}

// ============================ Pass 2: fold (one kernel, 128 blocks) ==========
// grid (8, BB). Block (bx,b): computes xbar, lm, P=lm⊙Wo redundantly (cheap),
// then G rows [16*bx, 16*bx+16). Block bx==0 additionally computes u, h.
__global__ void __launch_bounds__(256) k2_fold(
    const float* __restrict__ ln_w, const float* __restrict__ ln_b,
    const float* __restrict__ Wl,   const float* __restrict__ bl,
    const float* __restrict__ Wr,   const float* __restrict__ br,
    const float* __restrict__ Wo,   const float* __restrict__ bo) {
    __shared__ float sxa[2][DD];
    __shared__ float sx[DD];
    __shared__ float sr4[4][HH];
    __shared__ float slm[HH];
    __shared__ float sP[HH * EE];
    __shared__ float sWr[16 * HH];
    __shared__ float swv4[4][HH], sbv4[4][HH];

    int b = blockIdx.y, bx = blockIdx.x, tid = threadIdx.x;
    int d0 = bx * 16;

    // xbar (redundant per block)
    {
        int col = tid & 127, hf = tid >> 7;
        float s = 0.f;
        #pragma unroll 8
        for (int p = hf * 32; p < hf * 32 + 32; p++) s += d_partial[b][p][col];
        sxa[hf][col] = s;
    }
    // this block's 16 Wr rows
    #pragma unroll
    for (int i = tid; i < 16 * HH; i += 256)
        sWr[i] = Wr[(d0 + (i >> 6)) * HH + (i & 63)];
    __syncthreads();
    if (tid < DD)
        sx[tid] = ln_w[tid] * ((sxa[0][tid] + sxa[1][tid]) * (1.0f / NN)) + ln_b[tid];
    __syncthreads();

    // lm[h]: 4 threads per h, 32 d each
    {
        int h = tid & 63, q = tid >> 6;
        float a = 0.f;
        #pragma unroll 8
        for (int d = q * 32; d < q * 32 + 32; d++) a += sx[d] * Wl[d * HH + h];
        sr4[q][h] = a;
    }
    __syncthreads();
    if (tid < HH)
        slm[tid] = bl[tid] + sr4[0][tid] + sr4[1][tid] + sr4[2][tid] + sr4[3][tid];
    __syncthreads();

    // P[h][e] = lm[h]*Wo[h][e]
    #pragma unroll
    for (int i = tid; i < HH * EE; i += 256) sP[i] = slm[i >> 6] * Wo[i];
    __syncthreads();

    // G rows: thread -> (d_l = tid>>4, e0 = (tid&15)*4)
    {
        int d_l = tid >> 4, e0 = (tid & 15) * 4;
        float a0 = 0.f, a1 = 0.f, a2 = 0.f, a3 = 0.f;
        #pragma unroll 8
        for (int h = 0; h < HH; h++) {
            float wv = sWr[d_l * HH + h];
            const float* p = &sP[h * EE + e0];
            a0 += wv * p[0]; a1 += wv * p[1]; a2 += wv * p[2]; a3 += wv * p[3];
        }
        int d = d0 + d_l;
        float lw = ln_w[d];
        float* g = &d_G[b][d * EE + e0];
        g[0] = lw * a0; g[1] = lw * a1; g[2] = lw * a2; g[3] = lw * a3;
    }

    // block 0: u, h
    if (bx == 0) {
        {
            int h = tid & 63, q = tid >> 6;
            float aw = 0.f, ab = 0.f;
            #pragma unroll 8
            for (int d = q * 32; d < q * 32 + 32; d++) {
                float wr = Wr[d * HH + h];
                aw += ln_w[d] * wr;
                ab += ln_b[d] * wr;
            }
            swv4[q][h] = aw; sbv4[q][h] = ab;
        }
        __syncthreads();
        if (tid < EE) {
            int e = tid;
            float su = 0.f, sh = 0.f, sc = bo[e];
            #pragma unroll 8
            for (int h = 0; h < HH; h++) {
                float p  = sP[h * EE + e];
                float wv = swv4[0][h] + swv4[1][h] + swv4[2][h] + swv4[3][h];
                float bv = sbv4[0][h] + sbv4[1][h] + sbv4[2][h] + sbv4[3][h];
                su += wv * p;
                sh += bv * p;
                sc += br[h] * p;
            }
            d_u[b][e] = su;
            d_h[b][e] = sh + sc;
        }
    }
}

// ============================ Pass 3: fused main GEMM ========================
// out[b,n,e] = rstd_n*( (x_row @ G_b)[e] - mu_n*u[e] ) + h[e]
// 128 threads, 8 rows x 8 cols per thread (rows interleaved stride 16).
// This exact configuration measured fastest (R3).
#define K3_SMEM_FLOATS (DD * EE /*Gs*/ + TILE * XP /*Xs*/ + EE + EE + 2 * TILE)

__global__ void __launch_bounds__(128, 2) k3_gemm(const float* __restrict__ x,
                                                  float* __restrict__ out) {
    extern __shared__ float sm[];
    float*  Gs  = sm;                       // [DD][EE] row-major
    float*  Xs  = Gs + DD * EE;             // [TILE][XP]
    float*  su  = Xs + TILE * XP;           // [EE]
    float*  sh  = su + EE;                  // [EE]
    float2* sst = (float2*)(sh + EE);       // [TILE] {mu, rstd}

    int b    = blockIdx.y;
    int tile = blockIdx.x;
    int tid  = threadIdx.x;
    int row0 = tile * TILE;

    // load G (coalesced float4): 16 per thread
    {
        const float4* g4  = (const float4*)d_G[b];
        float4*       Gs4 = (float4*)Gs;
        #pragma unroll
        for (int i = 0; i < (DD * EE / 4) / 128; i++)
            Gs4[tid + i * 128] = g4[tid + i * 128];
    }
    // load X tile: 32 float4 per thread
    {
        const float4* xb = (const float4*)(x + ((size_t)b * NN + row0) * DD);
        #pragma unroll
        for (int i = 0; i < (TILE * DD / 4) / 128; i++) {
            int fid = tid + i * 128;
            int r = fid >> 5, kq = fid & 31;
            float4 v = xb[r * (DD / 4) + kq];
            *(float4*)&Xs[r * XP + 4 * kq] = v;
        }
    }
    if (tid < EE) { su[tid] = d_u[b][tid]; sh[tid] = d_h[b][tid]; }
    sst[tid] = d_stats[b * NN + row0 + tid];
    __syncthreads();

    int tx = tid & 7;        // 8 thread-cols (e)
    int ty = tid >> 3;       // 16 thread-rows; rows = ty + 16*i
    unsigned long long acc[8][4];     // [row][epair]
    #pragma unroll
    for (int i = 0; i < 8; i++)
        #pragma unroll
        for (int j = 0; j < 4; j++) acc[i][j] = 0ull;

    const float* xbase = &Xs[ty * XP];
    const float* gb    = &Gs[8 * tx];

    #pragma unroll 2
    for (int kc = 0; kc < DD / 4; kc++) {
        int k = 4 * kc;
        float4 xv[8];
        #pragma unroll
        for (int i = 0; i < 8; i++)
            xv[i] = *(const float4*)(xbase + i * (16 * XP) + k);
        #pragma unroll
        for (int kk = 0; kk < 4; kk++) {
            ulonglong2 g0 = *(const ulonglong2*)(gb + (k + kk) * EE);
            ulonglong2 g1 = *(const ulonglong2*)(gb + (k + kk) * EE + 4);
            #pragma unroll
            for (int i = 0; i < 8; i++) {
                float a = (kk == 0) ? xv[i].x : (kk == 1) ? xv[i].y
                        : (kk == 2) ? xv[i].z : xv[i].w;
                unsigned long long ap;
                asm("mov.b64 %0, {%1, %1};" : "=l"(ap) : "r"(__float_as_uint(a)));
                asm("fma.rn.f32x2 %0, %1, %2, %0;" : "+l"(acc[i][0]) : "l"(ap), "l"(g0.x));
                asm("fma.rn.f32x2 %0, %1, %2, %0;" : "+l"(acc[i][1]) : "l"(ap), "l"(g0.y));
                asm("fma.rn.f32x2 %0, %1, %2, %0;" : "+l"(acc[i][2]) : "l"(ap), "l"(g1.x));
                asm("fma.rn.f32x2 %0, %1, %2, %0;" : "+l"(acc[i][3]) : "l"(ap), "l"(g1.y));
            }
        }
    }

    // epilogue: out = rstd*(acc - mu*u) + h
    float u0[8], h0[8];
    #pragma unroll
    for (int j = 0; j < 8; j++) { u0[j] = su[8 * tx + j]; h0[j] = sh[8 * tx + j]; }
    #pragma unroll
    for (int i = 0; i < 8; i++) {
        int r = ty + 16 * i;
        float2 st = sst[r];
        float mu = st.x, rstd = st.y;
        float v[8];
        #pragma unroll
        for (int j = 0; j < 4; j++) {
            unsigned lo, hi;
            asm("mov.b64 {%0,%1}, %2;" : "=r"(lo), "=r"(hi) : "l"(acc[i][j]));
            v[2 * j]     = __uint_as_float(lo);
            v[2 * j + 1] = __uint_as_float(hi);
        }
        float* op = &out[(((size_t)b * NN + row0 + r) * EE) + 8 * tx];
        float4 o0, o1;
        o0.x = rstd * (v[0] - mu * u0[0]) + h0[0];
        o0.y = rstd * (v[1] - mu * u0[1]) + h0[1];
        o0.z = rstd * (v[2] - mu * u0[2]) + h0[2];
        o0.w = rstd * (v[3] - mu * u0[3]) + h0[3];
        o1.x = rstd * (v[4] - mu * u0[4]) + h0[4];
        o1.y = rstd * (v[5] - mu * u0[5]) + h0[5];
        o1.z = rstd * (v[6] - mu * u0[6]) + h0[6];
        o1.w = rstd * (v[7] - mu * u0[7]) + h0[7];
        *(float4*)(op + 0) = o0;
        *(float4*)(op + 4) = o1;
    }
}

// ============================ launch =========================================
extern "C" void kernel_launch(void* const* d_in, const int* in_sizes, int n_in,
                              void* d_out, int out_size) {
    const float* x    = (const float*)d_in[0];
    const float* ln_w = (const float*)d_in[1];
    const float* ln_b = (const float*)d_in[2];
    const float* Wl   = (const float*)d_in[3];
    const float* bl   = (const float*)d_in[4];
    const float* Wr   = (const float*)d_in[5];
    const float* br   = (const float*)d_in[6];
    const float* Wo   = (const float*)d_in[7];
    const float* bo   = (const float*)d_in[8];
    float* out = (float*)d_out;

    const int k3_smem = K3_SMEM_FLOATS * (int)sizeof(float);
    cudaFuncSetAttribute(k3_gemm, cudaFuncAttributeMaxDynamicSharedMemorySize, k3_smem);

    k1_stats<<<dim3(BLK1, BB), 256>>>(x);
    k2_fold<<<dim3(8, BB), 256>>>(ln_w, ln_b, Wl, bl, Wr, br, Wo, bo);
    k3_gemm<<<dim3(NN / TILE, BB), 128, k3_smem>>>(x, out);
}

// round 7
// speedup vs baseline: 2.4573x; 1.5649x over previous
#include <cuda_runtime.h>
#include <math.h>
#include <stdint.h>

// Problem shape (fixed by the dataset)
#define BB 16
#define NN 8192
#define DD 128
#define HH 64
#define EE 64
#define EPS_LN 1e-5f

#define BLK1 64               // blocks per batch in pass 1
#define ROWS1 (NN / BLK1)     // 128 rows per pass-1 block
#define TILE 128              // rows per pass-3 tile
#define XSP 132               // padded smem row stride (words)

// ---------------- scratch (__device__ globals; no allocation allowed) -------
__device__ float  d_partial[BB][BLK1][DD];  // per-block column sums of (x-mu)*rstd
__device__ float2 d_stats[BB * NN];         // per-row {mu, rstd}
__device__ float  d_Gt[BB][EE * DD];        // G^T: [e][d], G = diag(ln_w) Wr diag(lm) Wo
__device__ float  d_u[BB][EE];              // u = (ln_w@Wr ⊙ lm) @ Wo
__device__ float  d_h[BB][EE];              // h = (ln_b@Wr ⊙ lm) @ Wo + c

__device__ __forceinline__ uint32_t f2tf32(float v) {
    uint32_t r;
    asm("cvt.rna.tf32.f32 %0, %1;" : "=r"(r) : "f"(v));
    return r;
}
__device__ __forceinline__ void mma_tf32(float* c, const uint32_t* a,
                                         uint32_t b0, uint32_t b1) {
    asm volatile(
        "mma.sync.aligned.m16n8k8.row.col.f32.tf32.tf32.f32 "
        "{%0,%1,%2,%3}, {%4,%5,%6,%7}, {%8,%9}, {%0,%1,%2,%3};"
        : "+f"(c[0]), "+f"(c[1]), "+f"(c[2]), "+f"(c[3])
        : "r"(a[0]), "r"(a[1]), "r"(a[2]), "r"(a[3]), "r"(b0), "r"(b1));
}

// ============================ Pass 1: row stats + column sums ===============
__global__ void k1_stats(const float* __restrict__ x) {
    int b    = blockIdx.y;
    int w    = threadIdx.x >> 5;
    int lane = threadIdx.x & 31;
    int rp   = lane >> 3;     // row within 4-row group
    int c    = lane & 7;      // float4 column chunk
    int rowbase = blockIdx.x * ROWS1 + w * (ROWS1 / 8);

    const float4* xb = (const float4*)(x + (size_t)b * NN * DD);

    float4 acc[4];
    #pragma unroll
    for (int j = 0; j < 4; j++) acc[j] = make_float4(0.f, 0.f, 0.f, 0.f);

    #pragma unroll
    for (int it = 0; it < 4; it++) {
        int row = rowbase + it * 4 + rp;
        float4 v[4];
        #pragma unroll
        for (int j = 0; j < 4; j++)
            v[j] = xb[row * (DD / 4) + (c + 8 * j)];
        float s = 0.f, q = 0.f;
        #pragma unroll
        for (int j = 0; j < 4; j++) {
            s += v[j].x + v[j].y + v[j].z + v[j].w;
            q += v[j].x * v[j].x + v[j].y * v[j].y + v[j].z * v[j].z + v[j].w * v[j].w;
        }
        #pragma unroll
        for (int o = 4; o > 0; o >>= 1) {
            s += __shfl_xor_sync(0xffffffffu, s, o);
            q += __shfl_xor_sync(0xffffffffu, q, o);
        }
        float mu   = s * (1.0f / DD);
        float rstd = rsqrtf(q * (1.0f / DD) - mu * mu + EPS_LN);
        if (c == 0) d_stats[b * NN + row] = make_float2(mu, rstd);
        #pragma unroll
        for (int j = 0; j < 4; j++) {
            acc[j].x += (v[j].x - mu) * rstd;
            acc[j].y += (v[j].y - mu) * rstd;
            acc[j].z += (v[j].z - mu) * rstd;
            acc[j].w += (v[j].w - mu) * rstd;
        }
    }

    __shared__ float sred[32][DD];
    {
        float4* dst = (float4*)sred[w * 4 + rp];
        #pragma unroll
        for (int j = 0; j < 4; j++) dst[c + 8 * j] = acc[j];
    }
    __syncthreads();
    if (threadIdx.x < DD) {
        float s = 0.f;
        #pragma unroll
        for (int k = 0; k < 32; k++) s += sred[k][threadIdx.x];
        d_partial[b][blockIdx.x][threadIdx.x] = s;
    }
}

// ============================ Pass 2: fold (one kernel, 128 blocks) ==========
__global__ void __launch_bounds__(256) k2_fold(
    const float* __restrict__ ln_w, const float* __restrict__ ln_b,
    const float* __restrict__ Wl,   const float* __restrict__ bl,
    const float* __restrict__ Wr,   const float* __restrict__ br,
    const float* __restrict__ Wo,   const float* __restrict__ bo) {
    __shared__ float sxa[2][DD];
    __shared__ float sx[DD];
    __shared__ float sr4[4][HH];
    __shared__ float slm[HH];
    __shared__ float sP[HH * EE];
    __shared__ float sWr[16 * HH];
    __shared__ float swv4[4][HH], sbv4[4][HH];

    int b = blockIdx.y, bx = blockIdx.x, tid = threadIdx.x;
    int d0 = bx * 16;

    {
        int col = tid & 127, hf = tid >> 7;
        float s = 0.f;
        #pragma unroll 8
        for (int p = hf * 32; p < hf * 32 + 32; p++) s += d_partial[b][p][col];
        sxa[hf][col] = s;
    }
    #pragma unroll
    for (int i = tid; i < 16 * HH; i += 256)
        sWr[i] = Wr[(d0 + (i >> 6)) * HH + (i & 63)];
    __syncthreads();
    if (tid < DD)
        sx[tid] = ln_w[tid] * ((sxa[0][tid] + sxa[1][tid]) * (1.0f / NN)) + ln_b[tid];
    __syncthreads();

    {
        int h = tid & 63, q = tid >> 6;
        float a = 0.f;
        #pragma unroll 8
        for (int d = q * 32; d < q * 32 + 32; d++) a += sx[d] * Wl[d * HH + h];
        sr4[q][h] = a;
    }
    __syncthreads();
    if (tid < HH)
        slm[tid] = bl[tid] + sr4[0][tid] + sr4[1][tid] + sr4[2][tid] + sr4[3][tid];
    __syncthreads();

    #pragma unroll
    for (int i = tid; i < HH * EE; i += 256) sP[i] = slm[i >> 6] * Wo[i];
    __syncthreads();

    // G rows -> write TRANSPOSED into d_Gt[b][e*DD + d]
    {
        int d_l = tid >> 4, e0 = (tid & 15) * 4;
        float a0 = 0.f, a1 = 0.f, a2 = 0.f, a3 = 0.f;
        #pragma unroll 8
        for (int h = 0; h < HH; h++) {
            float wv = sWr[d_l * HH + h];
            const float* p = &sP[h * EE + e0];
            a0 += wv * p[0]; a1 += wv * p[1]; a2 += wv * p[2]; a3 += wv * p[3];
        }
        int d = d0 + d_l;
        float lw = ln_w[d];
        float* gt = d_Gt[b];
        gt[(e0 + 0) * DD + d] = lw * a0;
        gt[(e0 + 1) * DD + d] = lw * a1;
        gt[(e0 + 2) * DD + d] = lw * a2;
        gt[(e0 + 3) * DD + d] = lw * a3;
    }

    if (bx == 0) {
        {
            int h = tid & 63, q = tid >> 6;
            float aw = 0.f, ab = 0.f;
            #pragma unroll 8
            for (int d = q * 32; d < q * 32 + 32; d++) {
                float wr = Wr[d * HH + h];
                aw += ln_w[d] * wr;
                ab += ln_b[d] * wr;
            }
            swv4[q][h] = aw; sbv4[q][h] = ab;
        }
        __syncthreads();
        if (tid < EE) {
            int e = tid;
            float su = 0.f, sh = 0.f, sc = bo[e];
            #pragma unroll 8
            for (int h = 0; h < HH; h++) {
                float p  = sP[h * EE + e];
                float wv = swv4[0][h] + swv4[1][h] + swv4[2][h] + swv4[3][h];
                float bv = sbv4[0][h] + sbv4[1][h] + sbv4[2][h] + sbv4[3][h];
                su += wv * p;
                sh += bv * p;
                sc += br[h] * p;
            }
            d_u[b][e] = su;
            d_h[b][e] = sh + sc;
        }
    }
}

// ============================ Pass 3: mma.sync tf32 GEMM =====================
// D[128,64] = X_tile[128,128] @ G[128,64]; epilogue rstd*(D - mu*u) + h.
// 128 threads / 4 warps; warp w owns rows [32w, 32w+32), all 64 cols.
// m16n8k8 fragments loaded from padded row-major smem (conflict-free).
#define K3_SMEM_WORDS (TILE * XSP /*X tf32*/ + EE * XSP /*Gt tf32*/ + EE + EE + 2 * TILE)

__global__ void __launch_bounds__(128, 2) k3_mma(const float* __restrict__ x,
                                                 float* __restrict__ out) {
    extern __shared__ uint32_t sm[];
    uint32_t* Xs  = sm;                       // [TILE][XSP] tf32 bits
    uint32_t* Gts = Xs + TILE * XSP;          // [EE][XSP]  tf32 bits of G^T
    float*    su  = (float*)(Gts + EE * XSP); // [EE]
    float*    sh  = su + EE;                  // [EE]
    float2*   sst = (float2*)(sh + EE);       // [TILE] {mu, rstd}

    int b    = blockIdx.y;
    int tid  = threadIdx.x;
    int w    = tid >> 5, lane = tid & 31;
    int g    = lane >> 2, t = lane & 3;       // fragment group / in-group id
    int row0 = blockIdx.x * TILE;

    // ---- stage X (tf32) ----
    {
        const float4* xb = (const float4*)(x + ((size_t)b * NN + row0) * DD);
        #pragma unroll
        for (int i = 0; i < 32; i++) {
            int fid = tid + i * 128;          // 4096 float4 chunks
            int r = fid >> 5, cq = fid & 31;
            float4 v = xb[fid];
            uint4 tv = make_uint4(f2tf32(v.x), f2tf32(v.y), f2tf32(v.z), f2tf32(v.w));
            *(uint4*)&Xs[r * XSP + 4 * cq] = tv;
        }
    }
    // ---- stage G^T (tf32) ----
    {
        const float4* gt = (const float4*)d_Gt[b];
        #pragma unroll
        for (int i = 0; i < 16; i++) {
            int fid = tid + i * 128;          // 2048 chunks
            int e = fid >> 5, cq = fid & 31;
            float4 v = gt[fid];
            uint4 tv = make_uint4(f2tf32(v.x), f2tf32(v.y), f2tf32(v.z), f2tf32(v.w));
            *(uint4*)&Gts[e * XSP + 4 * cq] = tv;
        }
    }
    if (tid < EE) { su[tid] = d_u[b][tid]; sh[tid] = d_h[b][tid]; }
    sst[tid] = d_stats[b * NN + row0 + tid];
    __syncthreads();

    // ---- mainloop: 16 k-steps, 16 HMMA each ----
    float acc[2][8][4];
    #pragma unroll
    for (int mt = 0; mt < 2; mt++)
        #pragma unroll
        for (int nt = 0; nt < 8; nt++)
            #pragma unroll
            for (int j = 0; j < 4; j++) acc[mt][nt][j] = 0.f;

    int rA0 = w * 32 + g;        // rows rA0, rA0+8 (mt=0); +16 for mt=1
    #pragma unroll
    for (int ks = 0; ks < 16; ks++) {
        int k0 = ks * 8;
        uint32_t a[2][4];
        #pragma unroll
        for (int mt = 0; mt < 2; mt++) {
            const uint32_t* xr = &Xs[(rA0 + mt * 16) * XSP + k0 + t];
            a[mt][0] = xr[0];
            a[mt][1] = xr[8 * XSP];
            a[mt][2] = xr[4];
            a[mt][3] = xr[8 * XSP + 4];
        }
        #pragma unroll
        for (int nt = 0; nt < 8; nt++) {
            const uint32_t* gr = &Gts[(nt * 8 + g) * XSP + k0 + t];
            uint32_t b0 = gr[0], b1 = gr[4];
            mma_tf32(acc[0][nt], a[0], b0, b1);
            mma_tf32(acc[1][nt], a[1], b0, b1);
        }
    }

    // ---- epilogue: out = rstd*(acc - mu*u) + h ----
    #pragma unroll
    for (int mt = 0; mt < 2; mt++) {
        int rl = w * 32 + mt * 16 + g;        // local rows rl, rl+8
        float2 st0 = sst[rl];
        float2 st8 = sst[rl + 8];
        size_t ob0 = ((size_t)b * NN + row0 + rl) * EE;
        size_t ob8 = ob0 + 8 * EE;
        #pragma unroll
        for (int nt = 0; nt < 8; nt++) {
            int c = nt * 8 + t * 2;
            float2 uv = *(float2*)&su[c];
            float2 hv = *(float2*)&sh[c];
            float2 o0, o8;
            o0.x = st0.y * (acc[mt][nt][0] - st0.x * uv.x) + hv.x;
            o0.y = st0.y * (acc[mt][nt][1] - st0.x * uv.y) + hv.y;
            o8.x = st8.y * (acc[mt][nt][2] - st8.x * uv.x) + hv.x;
            o8.y = st8.y * (acc[mt][nt][3] - st8.x * uv.y) + hv.y;
            *(float2*)&out[ob0 + c] = o0;
            *(float2*)&out[ob8 + c] = o8;
        }
    }
}

// ============================ launch =========================================
extern "C" void kernel_launch(void* const* d_in, const int* in_sizes, int n_in,
                              void* d_out, int out_size) {
    const float* x    = (const float*)d_in[0];
    const float* ln_w = (const float*)d_in[1];
    const float* ln_b = (const float*)d_in[2];
    const float* Wl   = (const float*)d_in[3];
    const float* bl   = (const float*)d_in[4];
    const float* Wr   = (const float*)d_in[5];
    const float* br   = (const float*)d_in[6];
    const float* Wo   = (const float*)d_in[7];
    const float* bo   = (const float*)d_in[8];
    float* out = (float*)d_out;

    const int k3_smem = K3_SMEM_WORDS * (int)sizeof(uint32_t);
    cudaFuncSetAttribute(k3_mma, cudaFuncAttributeMaxDynamicSharedMemorySize, k3_smem);

    k1_stats<<<dim3(BLK1, BB), 256>>>(x);
    k2_fold<<<dim3(8, BB), 256>>>(ln_w, ln_b, Wl, bl, Wr, br, Wo, bo);
    k3_mma<<<dim3(NN / TILE, BB), 128, k3_smem>>>(x, out);
}